// round 7
// baseline (speedup 1.0000x reference)
#include <cuda_runtime.h>

#define N 4096
#define NN (N * N)
#define NITERS 300
#define NBLK 128
#define TPB 1024
#define TOL 3e-4f     // log2-units: max |dF| per sweep below this => converged

__device__ float  d_B[NN];      // raw distances, 64MB, L2-resident
__device__ float  d_F[N];
__device__ float  d_G[N];
__device__ double d_csum;
__device__ double d_emd;
__device__ float  d_k;          // log2(e)/eps
__device__ unsigned int g_bar;
__device__ unsigned int g_epoch;
__device__ unsigned int d_flag[2];

__device__ __forceinline__ float ex2f(float x) {
    float y;
    asm("ex2.approx.ftz.f32 %0, %1;" : "=f"(y) : "f"(x));
    return y;
}
__device__ __forceinline__ float ldcg(const float* p) { return __ldcg(p); }

// ---------------------------------------------------------------- init
__global__ void k_init() {
    d_csum  = 0.0;
    d_emd   = 0.0;
    g_bar   = 0u;
    g_epoch = 0u;
    d_flag[0] = 0u;
    d_flag[1] = 0u;
}

// ---------------------------------------------------------------- build C + csum; zero F/G
__global__ void k_build(const float* __restrict__ x, const float* __restrict__ y) {
    __shared__ float sred[8];
    int i = blockIdx.x;
    float x0 = x[3 * i], x1 = x[3 * i + 1], x2 = x[3 * i + 2];
    float xx = x0 * x0 + x1 * x1 + x2 * x2;
    float acc = 0.0f;
    for (int j = threadIdx.x; j < N; j += 256) {
        float y0 = y[3 * j], y1 = y[3 * j + 1], y2 = y[3 * j + 2];
        float yy  = y0 * y0 + y1 * y1 + y2 * y2;
        float dot = x0 * y0 + x1 * y1 + x2 * y2;
        float d2  = xx + yy - 2.0f * dot;
        float c   = sqrtf(fmaxf(d2, 0.0f) + 1e-12f);
        d_B[(size_t)i * N + j] = c;
        acc += c;
    }
    for (int o = 16; o; o >>= 1) acc += __shfl_down_sync(0xffffffffu, acc, o);
    if ((threadIdx.x & 31) == 0) sred[threadIdx.x >> 5] = acc;
    __syncthreads();
    if (threadIdx.x < 8) {
        acc = sred[threadIdx.x];
        for (int o = 4; o; o >>= 1) acc += __shfl_down_sync(0xffu, acc, o);
        if (threadIdx.x == 0) atomicAdd(&d_csum, (double)acc);
    }
    if (threadIdx.x == 0) { d_F[i] = 0.0f; d_G[i] = 0.0f; }
}

// ---------------------------------------------------------------- eps -> k
__global__ void k_eps() {
    double mean = d_csum / ((double)N * (double)N);
    d_k = (float)(1.4426950408889634 / (0.02 * mean));
}

// ---------------------------------------------------------------- grid barrier (no membar/IVALL)
__device__ __forceinline__ void gsync(unsigned int& ep) {
    __syncthreads();
    if (threadIdx.x == 0) {
        unsigned int t;
        asm volatile("atom.add.release.gpu.u32 %0, [%1], 1;"
                     : "=r"(t) : "l"(&g_bar) : "memory");
        if (t == NBLK - 1) {
            g_bar = 0u;
            asm volatile("st.release.gpu.u32 [%0], %1;"
                         :: "l"(&g_epoch), "r"(ep + 1u) : "memory");
        } else {
            unsigned int v;
            do {
                asm volatile("ld.acquire.gpu.u32 %0, [%1];"
                             : "=r"(v) : "l"(&g_epoch) : "memory");
            } while (v == ep);
        }
    }
    ep++;
    __syncthreads();
}

// ---------------------------------------------------------------- persistent Sinkhorn + final P*C
__global__ void __launch_bounds__(TPB, 1) k_persist(float* __restrict__ out) {
    __shared__ float sV[N];        // staged G (f pass) or F (g pass)
    __shared__ float sr[32][33];   // g-pass transpose-reduce / final block reduce
    const int tid = threadIdx.x;
    const int bid = blockIdx.x;
    const int wid = tid >> 5;
    const int ln  = tid & 31;
    const float k = d_k;
    unsigned int ep = 0u;

    for (int it = 0; it < NITERS; it++) {
        const int p = it & 1;

        // ---- f pass: warp-per-row.  F_i <- F_i - log2(sum_j 2^(G_j - k*B_ij + F_i - 12))
        for (int j = tid; j < N; j += TPB) sV[j] = ldcg(&d_G[j]);
        __syncthreads();
        {
            const int i = bid * 32 + wid;             // exactly one row per warp
            const float Fi = ldcg(&d_F[i]);
            const float c  = Fi - 12.0f;
            const float4* Br = (const float4*)(d_B + (size_t)i * N);
            const float4* V4 = (const float4*)sV;
            float s0 = 0.f, s1 = 0.f, s2 = 0.f, s3 = 0.f;
#pragma unroll 8
            for (int t = ln; t < N / 4; t += 32) {
                float4 b = Br[t];
                float4 g = V4[t];
                s0 += ex2f(fmaf(-k, b.x, g.x + c));
                s1 += ex2f(fmaf(-k, b.y, g.y + c));
                s2 += ex2f(fmaf(-k, b.z, g.z + c));
                s3 += ex2f(fmaf(-k, b.w, g.w + c));
            }
            float s = (s0 + s1) + (s2 + s3);
            for (int o = 16; o; o >>= 1) s += __shfl_down_sync(0xffffffffu, s, o);
            if (ln == 0) {
                float d = log2f(s);
                d_F[i] = Fi - d;
                if (fabsf(d) > TOL) d_flag[p] = 1u;   // benign race, same value
            }
        }
        gsync(ep);

        // ---- g pass: block-per-32-cols.  G_j <- G_j - log2(sum_i 2^(F_i - k*B_ij + G_j - 12))
        for (int i = tid; i < N; i += TPB) sV[i] = ldcg(&d_F[i]);
        __syncthreads();
        unsigned int conv;
        {
            const int tx = ln, ty = wid;              // warp = 32 consecutive cols, row-lane ty
            const int j  = bid * 32 + tx;
            const float Gj = ldcg(&d_G[j]);
            const float c  = Gj - 12.0f;
            const float* Bc = d_B + j;
            float s0 = 0.f, s1 = 0.f, s2 = 0.f, s3 = 0.f;
#pragma unroll 4
            for (int i = ty; i < N; i += 128) {
                s0 += ex2f(fmaf(-k, Bc[(size_t)i * N],        sV[i]      + c));
                s1 += ex2f(fmaf(-k, Bc[(size_t)(i + 32) * N], sV[i + 32] + c));
                s2 += ex2f(fmaf(-k, Bc[(size_t)(i + 64) * N], sV[i + 64] + c));
                s3 += ex2f(fmaf(-k, Bc[(size_t)(i + 96) * N], sV[i + 96] + c));
            }
            sr[ty][tx] = (s0 + s1) + (s2 + s3);
            // stable since gsync1: read this iteration's flag; zero the other buffer
            conv = __ldcg(&d_flag[p]);
            if (tid == 0) __stcg(&d_flag[p ^ 1], 0u);
            __syncthreads();
            float v = sr[tx][ty];                     // warp ty reduces column ty
            for (int o = 16; o; o >>= 1) v += __shfl_down_sync(0xffffffffu, v, o);
            if (tx == 0) {
                int jj = bid * 32 + ty;
                d_G[jj] = ldcg(&d_G[jj]) - log2f(v);
            }
        }
        gsync(ep);
        if (conv == 0u) break;                        // uniform across all blocks
    }

    // ---- final: sum_ij P_ij * C_ij,  P = 2^(F_i + G_j - k*B_ij - 24), C = B (raw)
    for (int j = tid; j < N; j += TPB) sV[j] = ldcg(&d_G[j]);
    __syncthreads();
    {
        const int i = bid * 32 + wid;
        const float c = ldcg(&d_F[i]) - 24.0f;
        const float4* Br = (const float4*)(d_B + (size_t)i * N);
        const float4* V4 = (const float4*)sV;
        float a0 = 0.f, a1 = 0.f, a2 = 0.f, a3 = 0.f;
#pragma unroll 8
        for (int t = ln; t < N / 4; t += 32) {
            float4 b = Br[t];
            float4 g = V4[t];
            a0 = fmaf(ex2f(fmaf(-k, b.x, g.x + c)), b.x, a0);
            a1 = fmaf(ex2f(fmaf(-k, b.y, g.y + c)), b.y, a1);
            a2 = fmaf(ex2f(fmaf(-k, b.z, g.z + c)), b.z, a2);
            a3 = fmaf(ex2f(fmaf(-k, b.w, g.w + c)), b.w, a3);
        }
        float s = (a0 + a1) + (a2 + a3);
        for (int o = 16; o; o >>= 1) s += __shfl_down_sync(0xffffffffu, s, o);
        if (ln == 0) sr[0][wid] = s;
    }
    __syncthreads();
    if (tid < 32) {
        float s = sr[0][tid];
        for (int o = 16; o; o >>= 1) s += __shfl_down_sync(0xffffffffu, s, o);
        if (tid == 0) atomicAdd(&d_emd, (double)s);
    }
    gsync(ep);
    if (bid == 0 && tid == 0) out[0] = (float)__ldcg((const double*)&d_emd);
}

// ---------------------------------------------------------------- launch
extern "C" void kernel_launch(void* const* d_in, const int* in_sizes, int n_in,
                              void* d_out, int out_size) {
    const float* x = (const float*)d_in[0];
    const float* y = (const float*)d_in[1];
    float* out = (float*)d_out;

    k_init<<<1, 1>>>();
    k_build<<<N, 256>>>(x, y);
    k_eps<<<1, 1>>>();
    k_persist<<<NBLK, TPB>>>(out);
}

// round 8
// speedup vs baseline: 1.8100x; 1.8100x over previous
#include <cuda_runtime.h>

#define N 4096
#define NN (N * N)
#define NITERS 300
#define NBLK 148
#define TPB 1024

__device__ float  d_B[NN];      // raw distances, 64MB, L2-resident
__device__ float  d_F[N];
__device__ float  d_G[N];
__device__ double d_csum;
__device__ double d_emd;
__device__ float  d_k;          // log2(e)/eps
__device__ unsigned int g_bar;
__device__ unsigned int g_epoch;

__device__ __forceinline__ float ex2f(float x) {
    float y;
    asm("ex2.approx.ftz.f32 %0, %1;" : "=f"(y) : "f"(x));
    return y;
}
__device__ __forceinline__ float ldcg(const float* p) { return __ldcg(p); }
__device__ __forceinline__ float4 ldcg4(const float4* p) { return __ldcg(p); }

// ---------------------------------------------------------------- init
__global__ void k_init() {
    d_csum  = 0.0;
    d_emd   = 0.0;
    g_bar   = 0u;
    g_epoch = 0u;
}

// ---------------------------------------------------------------- build C + csum; zero F/G
__global__ void k_build(const float* __restrict__ x, const float* __restrict__ y) {
    __shared__ float sred[8];
    int i = blockIdx.x;
    float x0 = x[3 * i], x1 = x[3 * i + 1], x2 = x[3 * i + 2];
    float xx = x0 * x0 + x1 * x1 + x2 * x2;
    float acc = 0.0f;
    for (int j = threadIdx.x; j < N; j += 256) {
        float y0 = y[3 * j], y1 = y[3 * j + 1], y2 = y[3 * j + 2];
        float yy  = y0 * y0 + y1 * y1 + y2 * y2;
        float dot = x0 * y0 + x1 * y1 + x2 * y2;
        float d2  = xx + yy - 2.0f * dot;
        float c   = sqrtf(fmaxf(d2, 0.0f) + 1e-12f);
        d_B[(size_t)i * N + j] = c;
        acc += c;
    }
    for (int o = 16; o; o >>= 1) acc += __shfl_down_sync(0xffffffffu, acc, o);
    if ((threadIdx.x & 31) == 0) sred[threadIdx.x >> 5] = acc;
    __syncthreads();
    if (threadIdx.x < 8) {
        acc = sred[threadIdx.x];
        for (int o = 4; o; o >>= 1) acc += __shfl_down_sync(0xffu, acc, o);
        if (threadIdx.x == 0) atomicAdd(&d_csum, (double)acc);
    }
    if (threadIdx.x == 0) { d_F[i] = 0.0f; d_G[i] = 0.0f; }
}

// ---------------------------------------------------------------- eps -> k
__global__ void k_eps() {
    double mean = d_csum / ((double)N * (double)N);
    d_k = (float)(1.4426950408889634 / (0.02 * mean));
}

// ---------------------------------------------------------------- grid barrier (no membar/IVALL)
__device__ __forceinline__ void gsync(unsigned int& ep) {
    __syncthreads();
    if (threadIdx.x == 0) {
        unsigned int t;
        asm volatile("atom.add.release.gpu.u32 %0, [%1], 1;"
                     : "=r"(t) : "l"(&g_bar) : "memory");
        if (t == NBLK - 1) {
            g_bar = 0u;
            asm volatile("st.release.gpu.u32 [%0], %1;"
                         :: "l"(&g_epoch), "r"(ep + 1u) : "memory");
        } else {
            unsigned int v;
            do {
                asm volatile("ld.acquire.gpu.u32 %0, [%1];"
                             : "=r"(v) : "l"(&g_epoch) : "memory");
            } while (v == ep);
        }
    }
    ep++;
    __syncthreads();
}

// ---------------------------------------------------------------- persistent Sinkhorn + final P*C
__global__ void __launch_bounds__(TPB, 1) k_persist(float* __restrict__ out) {
    __shared__ float sV[N];        // staged G (f pass) or F (g pass)
    __shared__ float sr[32][33];   // g-pass transpose-reduce / final block reduce
    const int tid = threadIdx.x;
    const int bid = blockIdx.x;
    const int wid = tid >> 5;
    const int ln  = tid & 31;
    const float k = d_k;
    const int frow = bid + NBLK * wid;     // round-robin row; valid if < N (27-28 rows/block)
    unsigned int ep = 0u;

    for (int it = 0; it < NITERS; it++) {
        // ---- f pass: warp-per-row.  F_i <- F_i - log2(sum_j 2^(G_j - k*B_ij + F_i - 12))
        for (int j = tid; j < N; j += TPB) sV[j] = ldcg(&d_G[j]);
        __syncthreads();
        if (frow < N) {
            const float Fi = ldcg(&d_F[frow]);
            const float c  = Fi - 12.0f;
            const float4* Br = (const float4*)(d_B + (size_t)frow * N);
            const float4* V4 = (const float4*)sV;
            float s0 = 0.f, s1 = 0.f, s2 = 0.f, s3 = 0.f;
#pragma unroll 8
            for (int t = ln; t < N / 4; t += 32) {
                float4 b = ldcg4(&Br[t]);
                float4 g = V4[t];
                s0 += ex2f(fmaf(-k, b.x, g.x + c));
                s1 += ex2f(fmaf(-k, b.y, g.y + c));
                s2 += ex2f(fmaf(-k, b.z, g.z + c));
                s3 += ex2f(fmaf(-k, b.w, g.w + c));
            }
            float s = (s0 + s1) + (s2 + s3);
            for (int o = 16; o; o >>= 1) s += __shfl_down_sync(0xffffffffu, s, o);
            if (ln == 0) d_F[frow] = Fi - log2f(s);
        }
        gsync(ep);

        // ---- g pass: 128 column tiles over blocks 0..127 (others pass through)
        if (bid < 128) {
            for (int i = tid; i < N; i += TPB) sV[i] = ldcg(&d_F[i]);
            __syncthreads();
            const int tx = ln, ty = wid;          // warp = 32 consecutive cols, row-lane ty
            const int j  = bid * 32 + tx;
            const float Gj = ldcg(&d_G[j]);
            const float c  = Gj - 12.0f;
            const float* Bc = d_B + j;
            float s0 = 0.f, s1 = 0.f, s2 = 0.f, s3 = 0.f;
#pragma unroll 8
            for (int i = ty; i < N; i += 128) {
                s0 += ex2f(fmaf(-k, ldcg(&Bc[(size_t)i * N]),        sV[i]      + c));
                s1 += ex2f(fmaf(-k, ldcg(&Bc[(size_t)(i + 32) * N]), sV[i + 32] + c));
                s2 += ex2f(fmaf(-k, ldcg(&Bc[(size_t)(i + 64) * N]), sV[i + 64] + c));
                s3 += ex2f(fmaf(-k, ldcg(&Bc[(size_t)(i + 96) * N]), sV[i + 96] + c));
            }
            sr[ty][tx] = (s0 + s1) + (s2 + s3);
            __syncthreads();
            float v = sr[tx][ty];                 // warp ty reduces column ty
            for (int o = 16; o; o >>= 1) v += __shfl_down_sync(0xffffffffu, v, o);
            if (tx == 0) {
                int jj = bid * 32 + ty;
                d_G[jj] = ldcg(&d_G[jj]) - log2f(v);
            }
        }
        gsync(ep);
    }

    // ---- final: sum_ij P_ij * C_ij,  P = 2^(F_i + G_j - k*B_ij - 24), C = B (raw)
    for (int j = tid; j < N; j += TPB) sV[j] = ldcg(&d_G[j]);
    __syncthreads();
    {
        float s = 0.f;
        if (frow < N) {
            const float c = ldcg(&d_F[frow]) - 24.0f;
            const float4* Br = (const float4*)(d_B + (size_t)frow * N);
            const float4* V4 = (const float4*)sV;
            float a0 = 0.f, a1 = 0.f, a2 = 0.f, a3 = 0.f;
#pragma unroll 8
            for (int t = ln; t < N / 4; t += 32) {
                float4 b = ldcg4(&Br[t]);
                float4 g = V4[t];
                a0 = fmaf(ex2f(fmaf(-k, b.x, g.x + c)), b.x, a0);
                a1 = fmaf(ex2f(fmaf(-k, b.y, g.y + c)), b.y, a1);
                a2 = fmaf(ex2f(fmaf(-k, b.z, g.z + c)), b.z, a2);
                a3 = fmaf(ex2f(fmaf(-k, b.w, g.w + c)), b.w, a3);
            }
            s = (a0 + a1) + (a2 + a3);
            for (int o = 16; o; o >>= 1) s += __shfl_down_sync(0xffffffffu, s, o);
        }
        if (ln == 0) sr[0][wid] = s;
    }
    __syncthreads();
    if (tid < 32) {
        float s = sr[0][tid];
        for (int o = 16; o; o >>= 1) s += __shfl_down_sync(0xffffffffu, s, o);
        if (tid == 0) atomicAdd(&d_emd, (double)s);
    }
    gsync(ep);
    if (bid == 0 && tid == 0) out[0] = (float)__ldcg((const double*)&d_emd);
}

// ---------------------------------------------------------------- launch
extern "C" void kernel_launch(void* const* d_in, const int* in_sizes, int n_in,
                              void* d_out, int out_size) {
    const float* x = (const float*)d_in[0];
    const float* y = (const float*)d_in[1];
    float* out = (float*)d_out;

    k_init<<<1, 1>>>();
    k_build<<<N, 256>>>(x, y);
    k_eps<<<1, 1>>>();
    k_persist<<<NBLK, TPB>>>(out);
}